// round 4
// baseline (speedup 1.0000x reference)
#include <cuda_runtime.h>

#define OUT_CH 16
#define PH 7
#define PW 7
#define SR 2
#define HH 80
#define WW 80
#define NPLANE (OUT_CH * PH * PW)        // 784 outputs per roi
#define N_ROIS 512
#define TOTAL  (N_ROIS * NPLANE)         // 401408 outputs
#define TPB    256
#define OUT_PER_BLK (TPB / 4)            // 64 outputs per block, 4 lanes each

__global__ void __launch_bounds__(TPB)
psroi_align_kernel(const float* __restrict__ feat,
                   const float* __restrict__ rois,
                   float* __restrict__ out) {
    const int t = blockIdx.x * TPB + threadIdx.x;
    const int o = t >> 2;                 // global output index
    const int s = t & 3;                  // sample point within bin (sy,sx)
    if (o >= TOTAL) return;

    const int n   = o / NPLANE;           // roi
    const int idx = o - n * NPLANE;       // channel = co*49 + ph*7 + pw
    const int rem = idx % (PH * PW);
    const int ph  = rem / PW;
    const int pw  = rem - ph * PW;

    // ROI params (few distinct rois per block -> L1 broadcast)
    const float* r = rois + (size_t)n * 5;
    const int   b  = (int)__ldg(r + 0);
    const float x1 = __ldg(r + 1) * (float)WW;
    const float y1 = __ldg(r + 2) * (float)HH;
    const float x2 = __ldg(r + 3) * (float)WW;
    const float y2 = __ldg(r + 4) * (float)HH;
    const float bh = fmaxf(y2 - y1, 0.1f) * (1.0f / (float)PH);
    const float bw = fmaxf(x2 - x1, 0.1f) * (1.0f / (float)PW);

    // this lane's sample point
    const float fy = (s & 2) ? 0.75f : 0.25f;
    const float fx = (s & 1) ? 0.75f : 0.25f;
    const float y  = y1 + ((float)ph + fy) * bh;
    const float x  = x1 + ((float)pw + fx) * bw;

    // branchless mask on unclipped coords (reference semantics)
    const float m = (y >= -1.0f && y <= (float)HH &&
                     x >= -1.0f && x <= (float)WW) ? 1.0f : 0.0f;

    const float yc = fminf(fmaxf(y, 0.0f), (float)(HH - 1));
    const float xc = fminf(fmaxf(x, 0.0f), (float)(WW - 1));
    const int y0 = (int)yc;               // yc >= 0, floor == trunc
    const int x0 = (int)xc;
    const int y1i = min(y0 + 1, HH - 1);
    const int x1i = min(x0 + 1, WW - 1);
    const float ly = yc - (float)y0, lx = xc - (float)x0;
    const float hy = 1.0f - ly,      hx = 1.0f - lx;

    const float* plane = feat + ((size_t)b * NPLANE + (size_t)idx) * (HH * WW);
    const float* r0 = plane + y0  * WW;
    const float* r1 = plane + y1i * WW;
    const float v00 = __ldg(r0 + x0);
    const float v01 = __ldg(r0 + x1i);
    const float v10 = __ldg(r1 + x0);
    const float v11 = __ldg(r1 + x1i);

    float v = m * (hy * (hx * v00 + lx * v01) + ly * (hx * v10 + lx * v11));

    // combine the 4 sample points of this output (lanes s=0..3)
    v += __shfl_xor_sync(0xffffffffu, v, 1);
    v += __shfl_xor_sync(0xffffffffu, v, 2);

    if (s == 0) out[o] = v * (1.0f / (SR * SR));
}

extern "C" void kernel_launch(void* const* d_in, const int* in_sizes, int n_in,
                              void* d_out, int out_size) {
    const float* feat = (const float*)d_in[0];
    const float* rois = (const float*)d_in[1];
    float* out = (float*)d_out;
    const int blocks = (TOTAL * 4 + TPB - 1) / TPB;   // 6272
    psroi_align_kernel<<<blocks, TPB>>>(feat, rois, out);
}

// round 6
// speedup vs baseline: 1.0508x; 1.0508x over previous
#include <cuda_runtime.h>

#define OUT_CH 16
#define PH 7
#define PW 7
#define SR 2
#define HH 80
#define WW 80
#define NPLANE (OUT_CH * PH * PW)        // 784 outputs per roi
#define N_ROIS 512
#define PARTS  8                         // blocks per roi
#define OPB    (NPLANE / PARTS)          // 98 outputs per block
#define TPB    (OPB * 4)                 // 392 threads (4 lanes per output)

// scratch (no allocation allowed)
__device__ float g_params[N_ROIS * 5];   // x1, y1, bh, bw, batch
__device__ int   g_perm[N_ROIS];         // rois sorted by batch index

// ── Kernel A: per-roi params + counting sort by batch (1 block) ──────────
__global__ void __launch_bounds__(N_ROIS)
roi_prep_kernel(const float* __restrict__ rois) {
    __shared__ int s_cnt[4];
    __shared__ int s_base[4];
    const int t = threadIdx.x;
    if (t < 4) s_cnt[t] = 0;
    __syncthreads();

    const float* r = rois + (size_t)t * 5;
    const int   b  = (int)r[0];
    const float x1 = r[1] * (float)WW;
    const float y1 = r[2] * (float)HH;
    const float x2 = r[3] * (float)WW;
    const float y2 = r[4] * (float)HH;
    float* p = g_params + (size_t)t * 5;
    p[0] = x1;
    p[1] = y1;
    p[2] = fmaxf(y2 - y1, 0.1f) * (1.0f / (float)PH);
    p[3] = fmaxf(x2 - x1, 0.1f) * (1.0f / (float)PW);
    p[4] = (float)b;

    const int rank = atomicAdd(&s_cnt[b], 1);
    __syncthreads();
    if (t == 0) {
        int acc = 0;
        for (int i = 0; i < 4; i++) { s_base[i] = acc; acc += s_cnt[i]; }
    }
    __syncthreads();
    g_perm[s_base[b] + rank] = t;
}

// ── Kernel B: main PSRoIAlign, batch-coherent block order ────────────────
__global__ void __launch_bounds__(TPB)
psroi_align_kernel(const float* __restrict__ feat,
                   float* __restrict__ out) {
    const int slot = blockIdx.x >> 3;         // sorted roi slot
    const int part = blockIdx.x & (PARTS - 1);
    const int n    = g_perm[slot];

    const float* p  = g_params + (size_t)n * 5;
    const float x1 = __ldg(p + 0);
    const float y1 = __ldg(p + 1);
    const float bh = __ldg(p + 2);
    const float bw = __ldg(p + 3);
    const int   b  = (int)__ldg(p + 4);

    const int q   = threadIdx.x >> 2;         // output within part (0..97)
    const int s   = threadIdx.x & 3;          // sample point (sy,sx)
    const int idx = part * OPB + q;           // channel = co*49 + ph*7 + pw
    const int rem = idx % (PH * PW);
    const int ph  = rem / PW;
    const int pw  = rem - ph * PW;

    const float fy = (s & 2) ? 0.75f : 0.25f;
    const float fx = (s & 1) ? 0.75f : 0.25f;
    const float y  = y1 + ((float)ph + fy) * bh;
    const float x  = x1 + ((float)pw + fx) * bw;

    // mask on UNCLIPPED coords (matches reference)
    const float m = (y >= -1.0f && y <= (float)HH &&
                     x >= -1.0f && x <= (float)WW) ? 1.0f : 0.0f;

    const float yc = fminf(fmaxf(y, 0.0f), (float)(HH - 1));
    const float xc = fminf(fmaxf(x, 0.0f), (float)(WW - 1));
    const int y0  = (int)yc;                  // yc >= 0 -> floor == trunc
    const int x0  = (int)xc;
    const int y1i = min(y0 + 1, HH - 1);
    const int x1i = min(x0 + 1, WW - 1);
    const float ly = yc - (float)y0, lx = xc - (float)x0;
    const float hy = 1.0f - ly,      hx = 1.0f - lx;

    const float* plane = feat + ((size_t)b * NPLANE + (size_t)idx) * (HH * WW);
    const float* r0 = plane + y0  * WW;
    const float* r1 = plane + y1i * WW;
    const float v00 = __ldg(r0 + x0);
    const float v01 = __ldg(r0 + x1i);
    const float v10 = __ldg(r1 + x0);
    const float v11 = __ldg(r1 + x1i);

    float v = m * (hy * (hx * v00 + lx * v01) + ly * (hx * v10 + lx * v11));

    // reduce the 4 sample points (lanes s=0..3) of this output
    v += __shfl_xor_sync(0xffffffffu, v, 1);
    v += __shfl_xor_sync(0xffffffffu, v, 2);

    if (s == 0) out[(size_t)n * NPLANE + idx] = v * (1.0f / (SR * SR));
}

extern "C" void kernel_launch(void* const* d_in, const int* in_sizes, int n_in,
                              void* d_out, int out_size) {
    const float* feat = (const float*)d_in[0];
    const float* rois = (const float*)d_in[1];
    float* out = (float*)d_out;
    roi_prep_kernel<<<1, N_ROIS>>>(rois);
    psroi_align_kernel<<<N_ROIS * PARTS, TPB>>>(feat, out);
}